// round 6
// baseline (speedup 1.0000x reference)
#include <cuda_runtime.h>

#define Bb 8
#define Nn 4096
#define NC 13
#define BN (Bb*Nn)        // 32768 points per set
#define TPB 128
#define ICN 16            // i-chunks per batch (256 rows each)
#define JCN 8             // j-chunks per batch (512 cols each)
#define IC 256            // rows per block
#define JC 512            // cols per block
#define JP 256            // col pairs per block
#define CHK 16            // jp per reduction chunk (32 j)
#define NCHUNK (JP/CHK)   // 16
#define NBLK (Bb*ICN*JCN) // 1024
#define ENC 0x7F800000    // k = ENC - float_bits(d); 0 == +inf; min d == max k
#define INFF 3.4e38f

typedef unsigned long long u64;

__device__ int          g_min[2*BN];      // [0,BN): row mins (rec->pt), [BN,2BN): col mins; zero==+inf, self-reset
__device__ float        g_rowpart[Bb*ICN];
__device__ float        g_colpart[Bb*JCN];
__device__ float        g_fpart[NBLK];    // per-block seg (picked) sums
__device__ unsigned int g_rowtk[Bb*ICN];  // zero-init, self-reset
__device__ unsigned int g_coltk[Bb*JCN];
__device__ unsigned int g_ticket;

// ---- f32x2 helpers ----------------------------------------------------------
__device__ __forceinline__ u64 pk(float lo, float hi) {
    u64 r; asm("mov.b64 %0, {%1, %2};" : "=l"(r) : "f"(lo), "f"(hi)); return r;
}
__device__ __forceinline__ u64 fma2(u64 a, u64 b, u64 c) {
    u64 d; asm("fma.rn.f32x2 %0, %1, %2, %3;" : "=l"(d) : "l"(a), "l"(b), "l"(c)); return d;
}
__device__ __forceinline__ u64 add2(u64 a, u64 b) {
    u64 d; asm("add.rn.f32x2 %0, %1, %2;" : "=l"(d) : "l"(a), "l"(b)); return d;
}
__device__ __forceinline__ void upk(u64 v, float& lo, float& hi) {
    asm("mov.b64 {%0, %1}, %2;" : "=f"(lo), "=f"(hi) : "l"(v));
}

// ---- single fused kernel ------------------------------------------------------
// grid (JCN, ICN, Bb) = (8,16,8), 128 threads
__global__ void __launch_bounds__(TPB, 7) fused_kernel(const float* __restrict__ rec,
                                                       const float* __restrict__ pt,
                                                       const float* __restrict__ prob,
                                                       const void* __restrict__ lab,
                                                       float* __restrict__ out) {
    __shared__ ulonglong2 scd[2*JP];       // 8KB candidates: pair p -> [2p]={xx',yy'} [2p+1]={zz',nn'}
    __shared__ float2     colp[CHK*129];   // per-thread col partials (padded rows)
    __shared__ float2     colp2[CHK*8];    // phase-B partials
    __shared__ float      sred[TPB];
    __shared__ int        s_is64, s_rowfin, s_colfin, s_last;

    const int jc = blockIdx.x, ic = blockIdx.y, b = blockIdx.z, t = threadIdx.x;
    const int bl = (b * ICN + ic) * JCN + jc;

    if (t == 0) { s_is64 = 1; s_rowfin = 0; s_colfin = 0; s_last = 0; }
    __syncthreads();
    // labels < 13; if int64 every odd 32-bit word is 0 (probe 128 labels)
    if (((const int*)lab)[2 * t + 1] != 0) s_is64 = 0;

    // queries (rec rows), full-distance form: chain starts at cn + qn
    u64 qx2[2], qy2[2], qz2[2], qn2[2];
    #pragma unroll
    for (int k = 0; k < 2; k++) {
        const float* p = rec + (size_t)(b * Nn + ic * IC + k * TPB + t) * 3;
        float x = p[0], y = p[1], z = p[2];
        float n = fmaf(x, x, fmaf(y, y, z * z));
        qx2[k] = pk(-2.f * x, -2.f * x);
        qy2[k] = pk(-2.f * y, -2.f * y);
        qz2[k] = pk(-2.f * z, -2.f * z);
        qn2[k] = pk(n, n);
    }
    // stage candidates (pt cols), pair-packed with norms
    #pragma unroll
    for (int r = 0; r < 2; r++) {
        int p = t + r * TPB;
        const float* c = pt + (size_t)(b * Nn + jc * JC + 2 * p) * 3;
        float x0 = c[0], y0 = c[1], z0 = c[2];
        float x1 = c[3], y1 = c[4], z1 = c[5];
        float n0 = fmaf(x0, x0, fmaf(y0, y0, z0 * z0));
        float n1 = fmaf(x1, x1, fmaf(y1, y1, z1 * z1));
        scd[2 * p]     = make_ulonglong2(pk(x0, x1), pk(y0, y1));
        scd[2 * p + 1] = make_ulonglong2(pk(z0, z1), pk(n0, n1));
    }
    __syncthreads();

    float ml0 = INFF, mh0 = INFF, ml1 = INFF, mh1 = INFF;

    for (int c = 0; c < NCHUNK; c++) {
        #pragma unroll
        for (int jl = 0; jl < CHK; jl++) {
            int jp = c * CHK + jl;
            ulonglong2 p0 = scd[2 * jp];
            ulonglong2 p1 = scd[2 * jp + 1];
            u64 t0 = fma2(qx2[0], p0.x, fma2(qy2[0], p0.y, fma2(qz2[0], p1.x, add2(p1.y, qn2[0]))));
            u64 t1 = fma2(qx2[1], p0.x, fma2(qy2[1], p0.y, fma2(qz2[1], p1.x, add2(p1.y, qn2[1]))));
            float lo0, hi0, lo1, hi1;
            upk(t0, lo0, hi0);
            upk(t1, lo1, hi1);
            ml0 = fminf(ml0, lo0); mh0 = fminf(mh0, hi0);
            ml1 = fminf(ml1, lo1); mh1 = fminf(mh1, hi1);
            colp[jl * 129 + t] = make_float2(fminf(lo0, lo1), fminf(hi0, hi1));
        }
        __syncthreads();
        {   // phase A: 8 threads per jp-column reduce 16 entries each
            int col = t & 15, s = t >> 4;
            float rl = INFF, rh = INFF;
            #pragma unroll
            for (int k = 0; k < 16; k++) {
                float2 v = colp[col * 129 + s * 16 + k];
                rl = fminf(rl, v.x); rh = fminf(rh, v.y);
            }
            colp2[col * 8 + s] = make_float2(rl, rh);
        }
        __syncthreads();
        if (t < CHK) {  // phase B: finish column, merge to global encoded min
            float cl = INFF, ch = INFF;
            #pragma unroll
            for (int k = 0; k < 8; k++) {
                float2 v = colp2[t * 8 + k];
                cl = fminf(cl, v.x); ch = fminf(ch, v.y);
            }
            int j = jc * JC + (c * CHK + t) * 2;
            int* gm = g_min + BN + b * Nn + j;
            atomicMax(gm,     ENC - __float_as_int(cl));
            atomicMax(gm + 1, ENC - __float_as_int(ch));
        }
        __syncthreads();
    }

    // row mins -> global encoded min
    {
        int ibase = b * Nn + ic * IC + t;
        atomicMax(g_min + ibase,       ENC - __float_as_int(fminf(ml0, mh0)));
        atomicMax(g_min + ibase + TPB, ENC - __float_as_int(fminf(ml1, mh1)));
    }

    // seg NLL: 32 points per block (warp 0)
    if (t < 32) {
        int idx = bl * 32 + t;
        int lb = s_is64 ? (int)((const long long*)lab)[idx] : ((const int*)lab)[idx];
        float v = prob[idx * NC + lb];
        #pragma unroll
        for (int off = 16; off > 0; off >>= 1)
            v += __shfl_xor_sync(0xffffffffu, v, off);
        if (t == 0) g_fpart[bl] = v;
    }

    __threadfence();
    if (t == 0) {
        if (atomicAdd(&g_rowtk[b * ICN + ic], 1u) == (unsigned)(JCN - 1)) s_rowfin = 1;
        if (atomicAdd(&g_coltk[b * JCN + jc], 1u) == (unsigned)(ICN - 1)) s_colfin = 1;
    }
    __syncthreads();

    if (s_rowfin) {   // sum this row-group's 256 mins; reset storage + counter
        __threadfence();
        int2* base = (int2*)(g_min + b * Nn + ic * IC);
        int2 v = base[t];
        sred[t] = __int_as_float(ENC - v.x) + __int_as_float(ENC - v.y);
        base[t] = make_int2(0, 0);
        __syncthreads();
        #pragma unroll
        for (int s = 64; s > 0; s >>= 1) {
            if (t < s) sred[t] += sred[t + s];
            __syncthreads();
        }
        if (t == 0) {
            g_rowpart[b * ICN + ic] = sred[0];
            g_rowtk[b * ICN + ic] = 0u;
        }
        __syncthreads();
    }
    if (s_colfin) {   // sum this col-group's 512 mins; reset storage + counter
        __threadfence();
        int4* base = (int4*)(g_min + BN + b * Nn + jc * JC);
        int4 v = base[t];
        sred[t] = (__int_as_float(ENC - v.x) + __int_as_float(ENC - v.y)) +
                  (__int_as_float(ENC - v.z) + __int_as_float(ENC - v.w));
        base[t] = make_int4(0, 0, 0, 0);
        __syncthreads();
        #pragma unroll
        for (int s = 64; s > 0; s >>= 1) {
            if (t < s) sred[t] += sred[t + s];
            __syncthreads();
        }
        if (t == 0) {
            g_colpart[b * JCN + jc] = sred[0];
            g_coltk[b * JCN + jc] = 0u;
        }
        __syncthreads();
    }

    __threadfence();
    if (t == 0) {
        if (atomicAdd(&g_ticket, 1u) == (unsigned)(NBLK - 1)) s_last = 1;
    }
    __syncthreads();

    if (s_last) {     // final deterministic combine
        __threadfence();
        float v = g_rowpart[t];                 // 128 entries
        if (t < Bb * JCN) v += g_colpart[t];    // 64 entries
        float sp = 0.f;
        #pragma unroll
        for (int k = 0; k < NBLK / TPB; k++)
            sp += g_fpart[t + k * TPB];
        sred[t] = v - sp;
        __syncthreads();
        #pragma unroll
        for (int s = 64; s > 0; s >>= 1) {
            if (t < s) sred[t] += sred[t + s];
            __syncthreads();
        }
        if (t == 0) {
            out[0] = sred[0] * (1.0f / (float)BN);
            g_ticket = 0u;   // reset for next graph replay
        }
    }
}

extern "C" void kernel_launch(void* const* d_in, const int* in_sizes, int n_in,
                              void* d_out, int out_size) {
    const float* seg_prob  = (const float*)d_in[0];
    const void*  seg_label = (const void*)d_in[1];
    const float* point_rec = (const float*)d_in[2];
    const float* point     = (const float*)d_in[3];

    fused_kernel<<<dim3(JCN, ICN, Bb), TPB>>>(point_rec, point, seg_prob, seg_label,
                                              (float*)d_out);
}